// round 1
// baseline (speedup 1.0000x reference)
#include <cuda_runtime.h>
#include <math.h>

// ---------------------------------------------------------------------------
// FormationOptimizer: fully-connected GNN, N=512, 3 message-passing rounds.
//
// Factorization: edge layer0 input is [nf[snd], nf[rcv], dist] @ ew0, which
// splits into A[i] + B[j] + dist*wd (+bias folded into B). Per-edge work then
// is relu + (128->64->32) MLP = 10240 MACs, done with packed fma.rn.f32x2.
// ---------------------------------------------------------------------------

#define NN 512
#define FD 64     // node feature dim
#define H0D 128
#define H1D 64
#define H2D 32

typedef unsigned long long ull;

// Scratch (no cudaMalloc allowed)
__device__ float g_NF[NN * FD];      // node features
__device__ float g_DIST[NN * NN];    // pairwise distances (constant across iters)
__device__ float g_A[NN * H0D];      // nf @ ew0[0:64]
__device__ float g_B[NN * H0D];      // nf @ ew0[64:128] + eb0
__device__ float g_AGG[NN * H2D];    // aggregated messages

__device__ __forceinline__ ull fma2(ull a, ull b, ull c) {
    ull d;
    asm("fma.rn.f32x2 %0, %1, %2, %3;" : "=l"(d) : "l"(a), "l"(b), "l"(c));
    return d;
}
__device__ __forceinline__ float2 unpack2(ull v) {
    float2 f;
    asm("mov.b64 {%0, %1}, %2;" : "=f"(f.x), "=f"(f.y) : "l"(v));
    return f;
}

// ---------------------------------------------------------------------------
// init: node features (states || objectives) + distance matrix
// ---------------------------------------------------------------------------
__global__ void k_init(const float* __restrict__ states, const float* __restrict__ obj) {
    int i = blockIdx.x, t = threadIdx.x;
    if (t < FD) g_NF[i * FD + t] = (t < 6) ? states[i * 6 + t] : obj[t - 6];
    float px = states[i * 6 + 0], py = states[i * 6 + 1], pz = states[i * 6 + 2];
    for (int j = t; j < NN; j += blockDim.x) {
        float dx = states[j * 6 + 0] - px;
        float dy = states[j * 6 + 1] - py;
        float dz = states[j * 6 + 2] - pz;
        g_DIST[i * NN + j] = sqrtf(dx * dx + dy * dy + dz * dz);
    }
}

// ---------------------------------------------------------------------------
// per-iteration node projections A, B (and zero AGG)
// grid = 512, block = 128 (thread = output column k)
// ---------------------------------------------------------------------------
__global__ void k_proj(const float* __restrict__ ew0, const float* __restrict__ eb0) {
    int i = blockIdx.x, k = threadIdx.x;
    __shared__ float snf[FD];
    if (k < FD) snf[k] = g_NF[i * FD + k];
    if (k < H2D) g_AGG[i * H2D + k] = 0.f;
    __syncthreads();
    float a = 0.f, b = 0.f;
#pragma unroll
    for (int c = 0; c < FD; c++) {
        float v = snf[c];
        a = fmaf(v, ew0[c * H0D + k], a);
        b = fmaf(v, ew0[(FD + c) * H0D + k], b);
    }
    g_A[i * H0D + k] = a;
    g_B[i * H0D + k] = b + eb0[k];
}

// ---------------------------------------------------------------------------
// edge kernel: CTA = (receiver j, half of senders). 2 tiles of 128 senders.
// SMEM layout (floats):
// ---------------------------------------------------------------------------
#define OFF_W1 0        // 128*64 float2 = 16384 floats (weights duplicated as (w,w))
#define OFF_W2 16384    // 64*32 float2  = 4096 floats
#define OFF_H0 20480    // 128 k x 130 (pad) edges
#define OFF_H1 37120    // 64 n x 130 (pad) edges
#define OFF_SB 45440    // 128
#define OFF_WD 45568    // 128
#define OFF_SD 45696    // 256
#define OFF_B1 45952    // 64
#define OFF_B2 46016    // 32
#define OFF_AG 46048    // 32
#define SMEM_FLOATS 46080

__global__ void __launch_bounds__(256, 1) k_edge(
    const float* __restrict__ ew0, const float* __restrict__ ew1,
    const float* __restrict__ eb1, const float* __restrict__ ew2,
    const float* __restrict__ eb2)
{
    extern __shared__ float sm[];
    float2* sW1 = (float2*)(sm + OFF_W1);
    float2* sW2 = (float2*)(sm + OFF_W2);
    float* sH0 = sm + OFF_H0;
    float* sH1 = sm + OFF_H1;
    float* sB  = sm + OFF_SB;
    float* sWd = sm + OFF_WD;
    float* sD  = sm + OFF_SD;
    float* sB1 = sm + OFF_B1;
    float* sB2 = sm + OFF_B2;
    float* sAg = sm + OFF_AG;

    const int t = threadIdx.x;
    const int j = blockIdx.x >> 1;
    const int half = blockIdx.x & 1;
    const int sbase0 = half * 256;

    // fill weights (duplicated for packed f32x2 FMA) + per-CTA vectors
    for (int idx = t; idx < H0D * H1D; idx += 256) {
        float w = ew1[idx];
        sW1[idx] = make_float2(w, w);
    }
    for (int idx = t; idx < H1D * H2D; idx += 256) {
        float w = ew2[idx];
        sW2[idx] = make_float2(w, w);
    }
    if (t < 128) { sB[t] = g_B[j * H0D + t]; sWd[t] = ew0[128 * H0D + t]; }
    sD[t] = g_DIST[j * NN + sbase0 + t];
    if (t < 64) sB1[t] = eb1[t];
    if (t < 32) { sB2[t] = eb2[t]; sAg[t] = 0.f; }
    __syncthreads();

    const int n4 = (t & 15) * 4;   // stage2: output columns n4..n4+3
    const int e8 = (t >> 4) * 8;   // stage2/3: edge rows e8..e8+7
    const int m2 = (t & 15) * 2;   // stage3: output columns m2..m2+1
    const int k1 = t & 127;        // stage1: hidden index
    const int eh = t >> 7;         // stage1: edge parity

    for (int tile = 0; tile < 2; tile++) {
        const int ibase = sbase0 + tile * 128;

        // ---- stage 1: H0[k][e] = relu(A[i][k] + B[j][k] + d*wd[k]) ----
        {
            const float bk = sB[k1], wdk = sWd[k1];
#pragma unroll 8
            for (int e = eh; e < 128; e += 2) {
                float a = g_A[(ibase + e) * H0D + k1];
                float h = fmaf(sD[tile * 128 + e], wdk, a + bk);
                sH0[k1 * 130 + e] = fmaxf(h, 0.f);
            }
        }
        __syncthreads();

        // ---- stage 2: H1 = relu(H0 @ W1 + b1), 128e x 64n, f32x2 packed ----
        {
            ull acc[4][4];
#pragma unroll
            for (int p = 0; p < 4; p++)
#pragma unroll
                for (int q = 0; q < 4; q++) acc[p][q] = 0ull;

#pragma unroll 2
            for (int k = 0; k < 128; k++) {
                const ulonglong2* wp = (const ulonglong2*)sW1 + ((k * 64 + n4) >> 1);
                ulonglong2 wa = wp[0];
                ulonglong2 wb = wp[1];
                const float* hrow = sH0 + k * 130 + e8;
                ull h0 = *(const ull*)(hrow + 0);
                ull h1 = *(const ull*)(hrow + 2);
                ull h2 = *(const ull*)(hrow + 4);
                ull h3 = *(const ull*)(hrow + 6);
                acc[0][0] = fma2(h0, wa.x, acc[0][0]);
                acc[0][1] = fma2(h0, wa.y, acc[0][1]);
                acc[0][2] = fma2(h0, wb.x, acc[0][2]);
                acc[0][3] = fma2(h0, wb.y, acc[0][3]);
                acc[1][0] = fma2(h1, wa.x, acc[1][0]);
                acc[1][1] = fma2(h1, wa.y, acc[1][1]);
                acc[1][2] = fma2(h1, wb.x, acc[1][2]);
                acc[1][3] = fma2(h1, wb.y, acc[1][3]);
                acc[2][0] = fma2(h2, wa.x, acc[2][0]);
                acc[2][1] = fma2(h2, wa.y, acc[2][1]);
                acc[2][2] = fma2(h2, wb.x, acc[2][2]);
                acc[2][3] = fma2(h2, wb.y, acc[2][3]);
                acc[3][0] = fma2(h3, wa.x, acc[3][0]);
                acc[3][1] = fma2(h3, wa.y, acc[3][1]);
                acc[3][2] = fma2(h3, wb.x, acc[3][2]);
                acc[3][3] = fma2(h3, wb.y, acc[3][3]);
            }
#pragma unroll
            for (int p = 0; p < 4; p++) {
                int e = e8 + 2 * p;
#pragma unroll
                for (int q = 0; q < 4; q++) {
                    float2 v = unpack2(acc[p][q]);
                    float bn = sB1[n4 + q];
                    sH1[(n4 + q) * 130 + e]     = fmaxf(v.x + bn, 0.f);
                    sH1[(n4 + q) * 130 + e + 1] = fmaxf(v.y + bn, 0.f);
                }
            }
        }
        __syncthreads();

        // ---- stage 3: H2 = relu(H1 @ W2 + b2), masked sum into sAg ----
        {
            ull acc[4][2];
#pragma unroll
            for (int p = 0; p < 4; p++) { acc[p][0] = 0ull; acc[p][1] = 0ull; }

#pragma unroll 2
            for (int n = 0; n < 64; n++) {
                ulonglong2 w = ((const ulonglong2*)sW2)[(n * 32 + m2) >> 1];
                const float* hrow = sH1 + n * 130 + e8;
                ull h0 = *(const ull*)(hrow + 0);
                ull h1 = *(const ull*)(hrow + 2);
                ull h2 = *(const ull*)(hrow + 4);
                ull h3 = *(const ull*)(hrow + 6);
                acc[0][0] = fma2(h0, w.x, acc[0][0]);
                acc[0][1] = fma2(h0, w.y, acc[0][1]);
                acc[1][0] = fma2(h1, w.x, acc[1][0]);
                acc[1][1] = fma2(h1, w.y, acc[1][1]);
                acc[2][0] = fma2(h2, w.x, acc[2][0]);
                acc[2][1] = fma2(h2, w.y, acc[2][1]);
                acc[3][0] = fma2(h3, w.x, acc[3][0]);
                acc[3][1] = fma2(h3, w.y, acc[3][1]);
            }
            float b0 = sB2[m2], b1 = sB2[m2 + 1];
            float pm0 = 0.f, pm1 = 0.f;
#pragma unroll
            for (int p = 0; p < 4; p++) {
                int i0 = ibase + e8 + 2 * p;
                float2 v0 = unpack2(acc[p][0]);
                float2 v1 = unpack2(acc[p][1]);
                if (i0 != j)     { pm0 += fmaxf(v0.x + b0, 0.f); pm1 += fmaxf(v1.x + b1, 0.f); }
                if (i0 + 1 != j) { pm0 += fmaxf(v0.y + b0, 0.f); pm1 += fmaxf(v1.y + b1, 0.f); }
            }
            atomicAdd(&sAg[m2], pm0);
            atomicAdd(&sAg[m2 + 1], pm1);
        }
        __syncthreads();
    }

    if (t < 32) atomicAdd(&g_AGG[j * H2D + t], sAg[t]);
}

// ---------------------------------------------------------------------------
// node MLP + residual: grid = 512, block = 128
// ---------------------------------------------------------------------------
__global__ void k_node(const float* __restrict__ nw0, const float* __restrict__ nb0,
                       const float* __restrict__ nw1, const float* __restrict__ nb1,
                       const float* __restrict__ nw2, const float* __restrict__ nb2,
                       const float* __restrict__ nwo, const float* __restrict__ nbo)
{
    int jn = blockIdx.x, t = threadIdx.x;
    __shared__ float y[96], h0[128], h1[64], h2[32];
    if (t < 64) y[t] = g_NF[jn * FD + t];
    else if (t < 96) y[t] = g_AGG[jn * H2D + (t - 64)];
    __syncthreads();
    {
        float acc = nb0[t];
#pragma unroll
        for (int c = 0; c < 96; c++) acc = fmaf(y[c], nw0[c * 128 + t], acc);
        h0[t] = fmaxf(acc, 0.f);
    }
    __syncthreads();
    if (t < 64) {
        float acc = nb1[t];
#pragma unroll
        for (int c = 0; c < 128; c++) acc = fmaf(h0[c], nw1[c * 64 + t], acc);
        h1[t] = fmaxf(acc, 0.f);
    }
    __syncthreads();
    if (t < 32) {
        float acc = nb2[t];
#pragma unroll
        for (int c = 0; c < 64; c++) acc = fmaf(h1[c], nw2[c * 32 + t], acc);
        h2[t] = fmaxf(acc, 0.f);
    }
    __syncthreads();
    if (t < 64) {
        float acc = nbo[t];
#pragma unroll
        for (int c = 0; c < 32; c++) acc = fmaf(h2[c], nwo[c * 64 + t], acc);
        g_NF[jn * FD + t] = y[t] + acc;
    }
}

// ---------------------------------------------------------------------------
// readout: out[j] = nf[j] @ rw + rb, grid = 4, block = 128
// ---------------------------------------------------------------------------
__global__ void k_read(const float* __restrict__ rw, const float* __restrict__ rb,
                       float* __restrict__ out)
{
    int jn = blockIdx.x * blockDim.x + threadIdx.x;
    if (jn >= NN) return;
    float a0 = rb[0], a1 = rb[1], a2 = rb[2];
#pragma unroll
    for (int c = 0; c < 64; c++) {
        float v = g_NF[jn * FD + c];
        a0 = fmaf(v, rw[c * 3 + 0], a0);
        a1 = fmaf(v, rw[c * 3 + 1], a1);
        a2 = fmaf(v, rw[c * 3 + 2], a2);
    }
    out[jn * 3 + 0] = a0;
    out[jn * 3 + 1] = a1;
    out[jn * 3 + 2] = a2;
}

// ---------------------------------------------------------------------------
extern "C" void kernel_launch(void* const* d_in, const int* in_sizes, int n_in,
                              void* d_out, int out_size)
{
    const float* states = (const float*)d_in[0];
    const float* obj    = (const float*)d_in[1];
    const float* ew0 = (const float*)d_in[2];
    const float* eb0 = (const float*)d_in[3];
    const float* ew1 = (const float*)d_in[4];
    const float* eb1 = (const float*)d_in[5];
    const float* ew2 = (const float*)d_in[6];
    const float* eb2 = (const float*)d_in[7];
    const float* nw0 = (const float*)d_in[8];
    const float* nb0 = (const float*)d_in[9];
    const float* nw1 = (const float*)d_in[10];
    const float* nb1 = (const float*)d_in[11];
    const float* nw2 = (const float*)d_in[12];
    const float* nb2 = (const float*)d_in[13];
    const float* nwo = (const float*)d_in[14];
    const float* nbo = (const float*)d_in[15];
    const float* rw  = (const float*)d_in[16];
    const float* rb  = (const float*)d_in[17];
    float* out = (float*)d_out;

    cudaFuncSetAttribute(k_edge, cudaFuncAttributeMaxDynamicSharedMemorySize,
                         SMEM_FLOATS * (int)sizeof(float));

    k_init<<<NN, 256>>>(states, obj);
    // num_message_passing = 3 (fixed by setup_inputs; graph needs a static loop)
    for (int it = 0; it < 3; it++) {
        k_proj<<<NN, 128>>>(ew0, eb0);
        k_edge<<<NN * 2, 256, SMEM_FLOATS * (int)sizeof(float)>>>(ew0, ew1, eb1, ew2, eb2);
        k_node<<<NN, 128>>>(nw0, nb0, nw1, nb1, nw2, nb2, nwo, nbo);
    }
    k_read<<<4, 128>>>(rw, rb, out);
}

// round 2
// speedup vs baseline: 1.6233x; 1.6233x over previous
#include <cuda_runtime.h>
#include <math.h>

// ---------------------------------------------------------------------------
// FormationOptimizer: fully-connected GNN, N=512, 3 message-passing rounds.
// Edge layer0 factorized: A[i] + B[j] + dist*wd. Per-edge MLP 128->64->32 via
// packed fma.rn.f32x2, n-pair packing (natural float2 weights, splatted h).
// ---------------------------------------------------------------------------

#define NN 512
#define FD 64
#define H0D 128
#define H1D 64
#define H2D 32

typedef unsigned long long ull;

__device__ float g_NF[NN * FD];
__device__ float g_DIST[NN * NN];
__device__ float g_A[NN * H0D];
__device__ float g_B[NN * H0D];
__device__ float g_AGG[NN * H2D];

__device__ __forceinline__ ull fma2(ull a, ull b, ull c) {
    ull d;
    asm("fma.rn.f32x2 %0, %1, %2, %3;" : "=l"(d) : "l"(a), "l"(b), "l"(c));
    return d;
}
__device__ __forceinline__ ull pack2(float x) {
    ull r;
    asm("mov.b64 %0, {%1, %1};" : "=l"(r) : "f"(x));
    return r;
}
__device__ __forceinline__ float2 unpack2(ull v) {
    float2 f;
    asm("mov.b64 {%0, %1}, %2;" : "=f"(f.x), "=f"(f.y) : "l"(v));
    return f;
}

// ---------------------------------------------------------------------------
__global__ void k_init(const float* __restrict__ states, const float* __restrict__ obj) {
    int i = blockIdx.x, t = threadIdx.x;
    if (t < FD) g_NF[i * FD + t] = (t < 6) ? states[i * 6 + t] : obj[t - 6];
    float px = states[i * 6 + 0], py = states[i * 6 + 1], pz = states[i * 6 + 2];
    for (int j = t; j < NN; j += blockDim.x) {
        float dx = states[j * 6 + 0] - px;
        float dy = states[j * 6 + 1] - py;
        float dz = states[j * 6 + 2] - pz;
        g_DIST[i * NN + j] = sqrtf(dx * dx + dy * dy + dz * dz);
    }
}

// ---------------------------------------------------------------------------
// k_proj: A = nf@ew0[0:64], B = nf@ew0[64:128]+eb0. 64 CTAs x 8 nodes.
// smem: sE[128*128] + snf[8*64]
// ---------------------------------------------------------------------------
#define PROJ_SMEM (16384 + 512)
__global__ void __launch_bounds__(256) k_proj(const float* __restrict__ ew0,
                                              const float* __restrict__ eb0) {
    extern __shared__ float sm[];
    float* sE = sm;
    float* snf = sm + 16384;
    const int t = threadIdx.x;
    const int nb8 = blockIdx.x * 8;

    for (int q = 0; q < 16; q++)
        *(float4*)(sE + q * 1024 + t * 4) = *(const float4*)(ew0 + q * 1024 + t * 4);
    for (int q = 0; q < 2; q++) {
        int idx = q * 256 + t;
        snf[idx] = g_NF[nb8 * 64 + idx];
    }
    g_AGG[blockIdx.x * 256 + t] = 0.f;
    __syncthreads();

    const int nd = t >> 5;
    const int k4 = (t & 31) * 4;
    float4 a = make_float4(0.f, 0.f, 0.f, 0.f);
    float4 b = make_float4(0.f, 0.f, 0.f, 0.f);
#pragma unroll 4
    for (int c = 0; c < 64; c++) {
        float v = snf[nd * 64 + c];
        float4 wa = *(const float4*)(sE + c * 128 + k4);
        float4 wb = *(const float4*)(sE + (64 + c) * 128 + k4);
        a.x = fmaf(v, wa.x, a.x); a.y = fmaf(v, wa.y, a.y);
        a.z = fmaf(v, wa.z, a.z); a.w = fmaf(v, wa.w, a.w);
        b.x = fmaf(v, wb.x, b.x); b.y = fmaf(v, wb.y, b.y);
        b.z = fmaf(v, wb.z, b.z); b.w = fmaf(v, wb.w, b.w);
    }
    float4 e = *(const float4*)(eb0 + k4);
    b.x += e.x; b.y += e.y; b.z += e.z; b.w += e.w;
    *(float4*)(g_A + (nb8 + nd) * 128 + k4) = a;
    *(float4*)(g_B + (nb8 + nd) * 128 + k4) = b;
}

// ---------------------------------------------------------------------------
// k_edge: grid = 512 receivers x 2 halves. Each CTA: 256 senders, 4 tiles of 64.
// 256 threads, 2 CTAs/SM.
// ---------------------------------------------------------------------------
#define OFF_W1 0          // 128*64
#define OFF_W2 8192       // 64*32
#define OFF_H0 10240      // 128*66
#define OFF_H1 18688      // 64*66
#define OFF_SB 22912      // 128
#define OFF_WD 23040      // 128
#define OFF_SD 23168      // 256
#define OFF_B1 23424      // 64
#define OFF_B2 23488      // 32
#define OFF_AG 23520      // 32
#define EDGE_SMEM 23552   // floats = 94208 bytes

__global__ void __launch_bounds__(256, 2) k_edge(
    const float* __restrict__ ew0, const float* __restrict__ ew1,
    const float* __restrict__ eb1, const float* __restrict__ ew2,
    const float* __restrict__ eb2)
{
    extern __shared__ float sm[];
    float* sW1 = sm + OFF_W1;
    float* sW2 = sm + OFF_W2;
    float* sH0 = sm + OFF_H0;
    float* sH1 = sm + OFF_H1;
    float* sB  = sm + OFF_SB;
    float* sWd = sm + OFF_WD;
    float* sD  = sm + OFF_SD;
    float* sB1 = sm + OFF_B1;
    float* sB2 = sm + OFF_B2;
    float* sAg = sm + OFF_AG;

    const int t = threadIdx.x;
    const int j = blockIdx.x >> 1;
    const int sbase0 = (blockIdx.x & 1) * 256;

    // stage weights + per-CTA vectors
#pragma unroll
    for (int q = 0; q < 8; q++)
        *(float4*)(sW1 + q * 1024 + t * 4) = *(const float4*)(ew1 + q * 1024 + t * 4);
#pragma unroll
    for (int q = 0; q < 2; q++)
        *(float4*)(sW2 + q * 1024 + t * 4) = *(const float4*)(ew2 + q * 1024 + t * 4);
    if (t < 128) { sB[t] = g_B[j * H0D + t]; sWd[t] = ew0[128 * H0D + t]; }
    sD[t] = g_DIST[j * NN + sbase0 + t];
    if (t < 64) sB1[t] = eb1[t];
    if (t < 32) { sB2[t] = eb2[t]; sAg[t] = 0.f; }
    __syncthreads();

    const int lane = t & 31;
    const int wrp  = t >> 5;
    const int e0 = lane * 2;       // stage2/3: 2 edges per thread
    const int nb = wrp * 8;        // stage2: 8 n columns per warp
    const int mb = wrp * 4;        // stage3: 4 m columns per warp
    const int k1 = t & 127;        // stage1: hidden index
    const int eh = (t >> 7) * 32;  // stage1: edge sub-range

    for (int tile = 0; tile < 4; tile++) {
        const int ibase = sbase0 + tile * 64;

        // ---- stage 1: H0[k][e] = relu(A[i][k] + B[j][k] + d*wd[k]) ----
        {
            const float bk = sB[k1], wdk = sWd[k1];
            const float* Ap = g_A + (ibase + eh) * H0D + k1;
            const float* dp = sD + (tile * 64) + eh;
            float* hp = sH0 + k1 * 66 + eh;
#pragma unroll 8
            for (int e = 0; e < 32; e++) {
                float a = Ap[e * H0D];
                float h = fmaf(dp[e], wdk, a + bk);
                hp[e] = fmaxf(h, 0.f);
            }
        }
        __syncthreads();

        // ---- stage 2: H1 = relu(H0 @ W1 + b1) ----
        {
            ull acc[2][4];
#pragma unroll
            for (int p = 0; p < 4; p++) { acc[0][p] = 0ull; acc[1][p] = 0ull; }

#pragma unroll 4
            for (int k = 0; k < 128; k++) {
                float2 h = *(const float2*)(sH0 + k * 66 + e0);
                ull hx = pack2(h.x);
                ull hy = pack2(h.y);
                ulonglong2 w0 = *(const ulonglong2*)(sW1 + k * 64 + nb);
                ulonglong2 w1 = *(const ulonglong2*)(sW1 + k * 64 + nb + 4);
                acc[0][0] = fma2(hx, w0.x, acc[0][0]);
                acc[0][1] = fma2(hx, w0.y, acc[0][1]);
                acc[0][2] = fma2(hx, w1.x, acc[0][2]);
                acc[0][3] = fma2(hx, w1.y, acc[0][3]);
                acc[1][0] = fma2(hy, w0.x, acc[1][0]);
                acc[1][1] = fma2(hy, w0.y, acc[1][1]);
                acc[1][2] = fma2(hy, w1.x, acc[1][2]);
                acc[1][3] = fma2(hy, w1.y, acc[1][3]);
            }
#pragma unroll
            for (int p = 0; p < 4; p++) {
                int n0 = nb + 2 * p;
                float b0 = sB1[n0], b1 = sB1[n0 + 1];
                float2 u0 = unpack2(acc[0][p]);   // edge e0:  (n0, n0+1)
                float2 u1 = unpack2(acc[1][p]);   // edge e0+1
                *(float2*)(sH1 + n0 * 66 + e0) =
                    make_float2(fmaxf(u0.x + b0, 0.f), fmaxf(u1.x + b0, 0.f));
                *(float2*)(sH1 + (n0 + 1) * 66 + e0) =
                    make_float2(fmaxf(u0.y + b1, 0.f), fmaxf(u1.y + b1, 0.f));
            }
        }
        __syncthreads();

        // ---- stage 3: H2 = relu(H1 @ W2 + b2), masked sum-aggregate ----
        {
            ull acc[2][2];
            acc[0][0] = acc[0][1] = acc[1][0] = acc[1][1] = 0ull;
#pragma unroll 4
            for (int n = 0; n < 64; n++) {
                float2 h = *(const float2*)(sH1 + n * 66 + e0);
                ull hx = pack2(h.x);
                ull hy = pack2(h.y);
                ulonglong2 w = *(const ulonglong2*)(sW2 + n * 32 + mb);
                acc[0][0] = fma2(hx, w.x, acc[0][0]);
                acc[0][1] = fma2(hx, w.y, acc[0][1]);
                acc[1][0] = fma2(hy, w.x, acc[1][0]);
                acc[1][1] = fma2(hy, w.y, acc[1][1]);
            }
            const bool me0 = (ibase + e0) != j;
            const bool me1 = (ibase + e0 + 1) != j;
            float pm[4];
#pragma unroll
            for (int p = 0; p < 2; p++) {
                int m0 = mb + 2 * p;
                float b0 = sB2[m0], b1 = sB2[m0 + 1];
                float2 u0 = unpack2(acc[0][p]);
                float2 u1 = unpack2(acc[1][p]);
                float s0 = 0.f, s1 = 0.f;
                if (me0) { s0 += fmaxf(u0.x + b0, 0.f); s1 += fmaxf(u0.y + b1, 0.f); }
                if (me1) { s0 += fmaxf(u1.x + b0, 0.f); s1 += fmaxf(u1.y + b1, 0.f); }
                pm[2 * p] = s0; pm[2 * p + 1] = s1;
            }
#pragma unroll
            for (int off = 16; off > 0; off >>= 1) {
#pragma unroll
                for (int q = 0; q < 4; q++)
                    pm[q] += __shfl_xor_sync(0xffffffffu, pm[q], off);
            }
            if (lane == 0) {
#pragma unroll
                for (int q = 0; q < 4; q++) sAg[mb + q] += pm[q];
            }
        }
        __syncthreads();
    }

    if (t < 32) atomicAdd(&g_AGG[j * H2D + t], sAg[t]);
}

// ---------------------------------------------------------------------------
// k_node: 64 CTAs x 8 nodes, weights staged in smem.
// ---------------------------------------------------------------------------
#define NOD_W0 0        // 96*128
#define NOD_W1 12288    // 128*64
#define NOD_W2 20480    // 64*32
#define NOD_WO 22528    // 32*64
#define NOD_Y  24576    // 8*96
#define NOD_H0 25344    // 8*128
#define NOD_H1 26368    // 8*64
#define NOD_H2 26880    // 8*32
#define NODE_SMEM 27136

__global__ void __launch_bounds__(256) k_node(
    const float* __restrict__ nw0, const float* __restrict__ nb0,
    const float* __restrict__ nw1, const float* __restrict__ nb1,
    const float* __restrict__ nw2, const float* __restrict__ nb2,
    const float* __restrict__ nwo, const float* __restrict__ nbo)
{
    extern __shared__ float sm[];
    float* sw0 = sm + NOD_W0;
    float* sw1 = sm + NOD_W1;
    float* sw2 = sm + NOD_W2;
    float* swo = sm + NOD_WO;
    float* sy  = sm + NOD_Y;
    float* sh0 = sm + NOD_H0;
    float* sh1 = sm + NOD_H1;
    float* sh2 = sm + NOD_H2;

    const int t = threadIdx.x;
    const int nb8 = blockIdx.x * 8;

#pragma unroll
    for (int q = 0; q < 12; q++)
        *(float4*)(sw0 + q * 1024 + t * 4) = *(const float4*)(nw0 + q * 1024 + t * 4);
#pragma unroll
    for (int q = 0; q < 8; q++)
        *(float4*)(sw1 + q * 1024 + t * 4) = *(const float4*)(nw1 + q * 1024 + t * 4);
#pragma unroll
    for (int q = 0; q < 2; q++)
        *(float4*)(sw2 + q * 1024 + t * 4) = *(const float4*)(nw2 + q * 1024 + t * 4);
#pragma unroll
    for (int q = 0; q < 2; q++)
        *(float4*)(swo + q * 1024 + t * 4) = *(const float4*)(nwo + q * 1024 + t * 4);
    // y = [nf | agg]
#pragma unroll
    for (int q = 0; q < 3; q++) {
        int idx = q * 256 + t;
        int nd = idx / 96, c = idx % 96;
        sy[idx] = (c < 64) ? g_NF[(nb8 + nd) * 64 + c]
                           : g_AGG[(nb8 + nd) * 32 + (c - 64)];
    }
    __syncthreads();

    const int nd = t >> 5;
    const int lane = t & 31;
    // layer 0: 96 -> 128
    {
        const int o4 = lane * 4;
        float4 acc = *(const float4*)(nb0 + o4);
#pragma unroll 4
        for (int c = 0; c < 96; c++) {
            float v = sy[nd * 96 + c];
            float4 w = *(const float4*)(sw0 + c * 128 + o4);
            acc.x = fmaf(v, w.x, acc.x); acc.y = fmaf(v, w.y, acc.y);
            acc.z = fmaf(v, w.z, acc.z); acc.w = fmaf(v, w.w, acc.w);
        }
        acc.x = fmaxf(acc.x, 0.f); acc.y = fmaxf(acc.y, 0.f);
        acc.z = fmaxf(acc.z, 0.f); acc.w = fmaxf(acc.w, 0.f);
        *(float4*)(sh0 + nd * 128 + o4) = acc;
    }
    __syncthreads();
    // layer 1: 128 -> 64
    {
        const int o2 = lane * 2;
        float2 acc = *(const float2*)(nb1 + o2);
#pragma unroll 4
        for (int c = 0; c < 128; c++) {
            float v = sh0[nd * 128 + c];
            float2 w = *(const float2*)(sw1 + c * 64 + o2);
            acc.x = fmaf(v, w.x, acc.x); acc.y = fmaf(v, w.y, acc.y);
        }
        acc.x = fmaxf(acc.x, 0.f); acc.y = fmaxf(acc.y, 0.f);
        *(float2*)(sh1 + nd * 64 + o2) = acc;
    }
    __syncthreads();
    // layer 2: 64 -> 32
    {
        float acc = nb2[lane];
#pragma unroll 4
        for (int c = 0; c < 64; c++)
            acc = fmaf(sh1[nd * 64 + c], sw2[c * 32 + lane], acc);
        sh2[nd * 32 + lane] = fmaxf(acc, 0.f);
    }
    __syncthreads();
    // output: 32 -> 64, residual
    {
        const int o2 = lane * 2;
        float2 acc = *(const float2*)(nbo + o2);
#pragma unroll 4
        for (int c = 0; c < 32; c++) {
            float v = sh2[nd * 32 + c];
            float2 w = *(const float2*)(swo + c * 64 + o2);
            acc.x = fmaf(v, w.x, acc.x); acc.y = fmaf(v, w.y, acc.y);
        }
        float2 y;
        y.x = sy[nd * 96 + o2] + acc.x;
        y.y = sy[nd * 96 + o2 + 1] + acc.y;
        *(float2*)(g_NF + (nb8 + nd) * 64 + o2) = y;
    }
}

// ---------------------------------------------------------------------------
__global__ void k_read(const float* __restrict__ rw, const float* __restrict__ rb,
                       float* __restrict__ out)
{
    int jn = blockIdx.x * blockDim.x + threadIdx.x;
    if (jn >= NN) return;
    float a0 = rb[0], a1 = rb[1], a2 = rb[2];
#pragma unroll
    for (int c = 0; c < 64; c++) {
        float v = g_NF[jn * FD + c];
        a0 = fmaf(v, rw[c * 3 + 0], a0);
        a1 = fmaf(v, rw[c * 3 + 1], a1);
        a2 = fmaf(v, rw[c * 3 + 2], a2);
    }
    out[jn * 3 + 0] = a0;
    out[jn * 3 + 1] = a1;
    out[jn * 3 + 2] = a2;
}

// ---------------------------------------------------------------------------
extern "C" void kernel_launch(void* const* d_in, const int* in_sizes, int n_in,
                              void* d_out, int out_size)
{
    const float* states = (const float*)d_in[0];
    const float* obj    = (const float*)d_in[1];
    const float* ew0 = (const float*)d_in[2];
    const float* eb0 = (const float*)d_in[3];
    const float* ew1 = (const float*)d_in[4];
    const float* eb1 = (const float*)d_in[5];
    const float* ew2 = (const float*)d_in[6];
    const float* eb2 = (const float*)d_in[7];
    const float* nw0 = (const float*)d_in[8];
    const float* nb0 = (const float*)d_in[9];
    const float* nw1 = (const float*)d_in[10];
    const float* nb1 = (const float*)d_in[11];
    const float* nw2 = (const float*)d_in[12];
    const float* nb2 = (const float*)d_in[13];
    const float* nwo = (const float*)d_in[14];
    const float* nbo = (const float*)d_in[15];
    const float* rw  = (const float*)d_in[16];
    const float* rb  = (const float*)d_in[17];
    float* out = (float*)d_out;

    cudaFuncSetAttribute(k_edge, cudaFuncAttributeMaxDynamicSharedMemorySize,
                         EDGE_SMEM * (int)sizeof(float));
    cudaFuncSetAttribute(k_proj, cudaFuncAttributeMaxDynamicSharedMemorySize,
                         PROJ_SMEM * (int)sizeof(float));
    cudaFuncSetAttribute(k_node, cudaFuncAttributeMaxDynamicSharedMemorySize,
                         NODE_SMEM * (int)sizeof(float));

    k_init<<<NN, 256>>>(states, obj);
    for (int it = 0; it < 3; it++) {
        k_proj<<<64, 256, PROJ_SMEM * (int)sizeof(float)>>>(ew0, eb0);
        k_edge<<<NN * 2, 256, EDGE_SMEM * (int)sizeof(float)>>>(ew0, ew1, eb1, ew2, eb2);
        k_node<<<64, 256, NODE_SMEM * (int)sizeof(float)>>>(nw0, nb0, nw1, nb1,
                                                            nw2, nb2, nwo, nbo);
    }
    k_read<<<4, 128>>>(rw, rb, out);
}